// round 6
// baseline (speedup 1.0000x reference)
#include <cuda_runtime.h>
#include <cuda_fp16.h>
#include <cstdint>
#include <cstddef>

// ---------------- problem dims ----------------
#define B_ROWS 8192
#define K_DIM  4096
#define N_DIM  4096

// ---------------- GEMM tiling -----------------
#define TM 128
#define TN 128
#define KC 64                         // K elems per stage
#define NSTAGE 4
#define KSTAGES (K_DIM / KC)          // 64
// stage layout: A-hi fp16 fragments 16KB | B-hi 16KB | A-lo s8 8KB | B-lo 8KB
#define AH_OFF 0
#define BH_OFF 16384
#define AL_OFF 32768
#define BL_OFF 40960
#define STG_BYTES 49152
#define SMEM_DYN (1024 + NSTAGE * STG_BYTES)   // 197632
#define NTHREADS 256                  // 8 compute warps, 4(m) x 2(n), warp tile 32x64

// ---------------- device scratch ----------------
__device__ __align__(1024) unsigned char g_xhi[(size_t)B_ROWS * K_DIM * 2];  // 64MB fp16 frags
__device__ __align__(1024) unsigned char g_xlo[(size_t)B_ROWS * K_DIM];     // 32MB s8 frags
__device__ __align__(1024) unsigned char g_whi[(size_t)N_DIM * K_DIM * 2];  // 32MB fp16 frags
__device__ __align__(1024) unsigned char g_wlo[(size_t)N_DIM * K_DIM];      // 16MB s8 frags
__device__ float g_out[(size_t)B_ROWS * N_DIM];                              // 128MB
__device__ float g_s2[B_ROWS];
__device__ float g_fc_sf[N_DIM];
__device__ float g_bias_sf[N_DIM];
__device__ float g_b_int[N_DIM];
__device__ unsigned int g_max_bits;
__device__ float g_act_sf;

// ---------------- PTX helpers (baseline ISA only) ----------------
__device__ __forceinline__ uint32_t smem_u32(const void* p) {
    return (uint32_t)__cvta_generic_to_shared(p);
}

#define MBAR_INIT(addr, cnt) \
    asm volatile("mbarrier.init.shared.b64 [%0], %1;" :: "r"(addr), "r"(cnt) : "memory")
#define MBAR_EXPECT_TX(addr, tx) \
    asm volatile("mbarrier.arrive.expect_tx.shared.b64 _, [%0], %1;" :: "r"(addr), "r"(tx) : "memory")

#define MBAR_WAIT(mbar_smem_addr, phase_parity) do { \
    uint32_t _mbar = (uint32_t)(mbar_smem_addr); \
    uint32_t _parity = (uint32_t)(phase_parity); \
    uint32_t _done; \
    asm volatile( \
        "{\n\t.reg .pred p;\n\t" \
        "mbarrier.try_wait.parity.acquire.cta.shared::cta.b64 p, [%1], %2;\n\t" \
        "selp.b32 %0, 1, 0, p;\n\t}" \
        : "=r"(_done) : "r"(_mbar), "r"(_parity) : "memory"); \
    if (!_done) { \
        asm volatile( \
            "{\n\t.reg .pred P1;\n\t" \
            "WAIT_LOOP_%=:\n\t" \
            "mbarrier.try_wait.parity.acquire.cta.shared::cta.b64 P1, [%0], %1, 0x989680;\n\t" \
            "@P1 bra.uni WAIT_DONE_%=;\n\t" \
            "bra.uni WAIT_LOOP_%=;\n\t" \
            "WAIT_DONE_%=:\n\t}" \
            :: "r"(_mbar), "r"(_parity) : "memory"); \
    } \
} while (0)

#define BULK_G2S(dst, src, nbytes, mbar) \
    asm volatile("cp.async.bulk.shared::cluster.global.mbarrier::complete_tx::bytes [%0], [%1], %2, [%3];" \
        :: "r"(dst), "l"(src), "r"(nbytes), "r"(mbar) : "memory")

#define LDS128(r, addr) \
    asm volatile("ld.shared.v4.b32 {%0,%1,%2,%3}, [%4];" \
        : "=r"((r)[0]), "=r"((r)[1]), "=r"((r)[2]), "=r"((r)[3]) : "r"(addr))
#define LDS64(r0, r1, addr) \
    asm volatile("ld.shared.v2.b32 {%0,%1}, [%2];" : "=r"(r0), "=r"(r1) : "r"(addr))

__device__ __forceinline__ void mma16816(float* c, const uint32_t* a, uint32_t b0, uint32_t b1) {
    asm volatile("mma.sync.aligned.m16n8k16.row.col.f32.f16.f16.f32 "
                 "{%0,%1,%2,%3}, {%4,%5,%6,%7}, {%8,%9}, {%0,%1,%2,%3};"
                 : "+f"(c[0]), "+f"(c[1]), "+f"(c[2]), "+f"(c[3])
                 : "r"(a[0]), "r"(a[1]), "r"(a[2]), "r"(a[3]), "r"(b0), "r"(b1));
}
__device__ __forceinline__ void imma16832(int* c, const uint32_t* a, uint32_t b0, uint32_t b1) {
    asm volatile("mma.sync.aligned.m16n8k32.row.col.s32.s8.s8.s32 "
                 "{%0,%1,%2,%3}, {%4,%5,%6,%7}, {%8,%9}, {%0,%1,%2,%3};"
                 : "+r"(c[0]), "+r"(c[1]), "+r"(c[2]), "+r"(c[3])
                 : "r"(a[0]), "r"(a[1]), "r"(a[2]), "r"(a[3]), "r"(b0), "r"(b1));
}

__device__ __forceinline__ uint32_t pack_s8x4(int a, int b, int c, int d) {
    return (uint32_t)(a & 0xFF) | ((uint32_t)(b & 0xFF) << 8) |
           ((uint32_t)(c & 0xFF) << 16) | ((uint32_t)(d & 0xFF) << 24);
}

// =====================================================================
// K1: W prep. Block per output row o; thread t owns k = 16t..16t+15.
//     absmax -> fc_sf/bias_sf/b_int; emit fp16 + s8 fragments.
// =====================================================================
__global__ void __launch_bounds__(256) k_wprep(const float* __restrict__ W,
                                               const float* __restrict__ b,
                                               const float* __restrict__ asf,
                                               float* __restrict__ out_fc) {
    __shared__ float red[8];
    __shared__ float fc_sh;
    int o = blockIdx.x;
    int t = threadIdx.x;
    int lane = t & 31, wrp = t >> 5;

    const float4* w4 = reinterpret_cast<const float4*>(W + (size_t)o * K_DIM) + t * 4;
    float4 v[4];
#pragma unroll
    for (int j = 0; j < 4; j++) v[j] = __ldg(w4 + j);

    float am = 0.f;
#pragma unroll
    for (int j = 0; j < 4; j++)
        am = fmaxf(am, fmaxf(fmaxf(fabsf(v[j].x), fabsf(v[j].y)),
                             fmaxf(fabsf(v[j].z), fabsf(v[j].w))));
#pragma unroll
    for (int off = 16; off > 0; off >>= 1)
        am = fmaxf(am, __shfl_xor_sync(0xFFFFFFFFu, am, off));
    if (lane == 0) red[wrp] = am;
    __syncthreads();
    if (t == 0) {
        float m = red[0];
#pragma unroll
        for (int j = 1; j < 8; j++) m = fmaxf(m, red[j]);
        float fc = __fdiv_rn(fmaxf(m, 1e-8f), 127.0f);
        float a  = __ldg(asf);
        float bs = __fmul_rn(fc, a);
        fc_sh = fc;
        g_fc_sf[o]   = fc;
        g_bias_sf[o] = bs;
        g_b_int[o]   = rintf(__fdiv_rn(__ldg(b + o), bs));
        out_fc[o]    = fc;
        if (o == 0) g_max_bits = 0u;
    }
    __syncthreads();
    float fc = fc_sh;

    float vv[16] = {v[0].x, v[0].y, v[0].z, v[0].w, v[1].x, v[1].y, v[1].z, v[1].w,
                    v[2].x, v[2].y, v[2].z, v[2].w, v[3].x, v[3].y, v[3].z, v[3].w};
    unsigned us[16];
    int wi[16];
#pragma unroll
    for (int i = 0; i < 16; i++) {
        float r = fminf(fmaxf(rintf(__fdiv_rn(vv[i], fc)), -128.f), 127.f);
        us[i] = (unsigned)__half_as_ushort(__float2half_rn(r));
        wi[i] = (int)r;
    }

    int tn = o >> 7;
    int nb = (o & 127) >> 3;
    int g  = o & 7;
    int ks = t >> 2, kk = t & 3, kstep = (t >> 1) & 1, khalf = t & 1;

    // B-hi fragments: [kk][nblock16][lane][8B]
    unsigned char* whi = g_whi + ((size_t)(tn * KSTAGES + ks) << 14);
#pragma unroll
    for (int p = 0; p < 8; p++) {
        int lan = g * 4 + (p & 3);
        int reg = p >> 2;
        *reinterpret_cast<uint32_t*>(whi + kk * 4096 + nb * 256 + lan * 8 + reg * 4) =
            us[2 * p] | (us[2 * p + 1] << 16);
    }
    // B-lo fragments: [kstep][nblock16][lane][8B]
    unsigned char* wlo = g_wlo + ((size_t)(tn * KSTAGES + ks) << 13);
#pragma unroll
    for (int q = 0; q < 4; q++) {
        int lan = g * 4 + q;
        *reinterpret_cast<uint32_t*>(wlo + kstep * 4096 + nb * 256 + lan * 8 + khalf * 4) =
            pack_s8x4(wi[4 * q], wi[4 * q + 1], wi[4 * q + 2], wi[4 * q + 3]);
    }
}

// =====================================================================
// K2: X prep. Block per row m. x_int = x/act_sf; hi = fp16(x_int);
//     lo = x_int - hi quantized to s8 with per-row scale s2.
// =====================================================================
__global__ void __launch_bounds__(256) k_packx(const float* __restrict__ X,
                                               const float* __restrict__ asf) {
    __shared__ float red[8];
    __shared__ float s2_sh;
    int m = blockIdx.x;
    int t = threadIdx.x;
    int lane = t & 31, wrp = t >> 5;

    const float4* x4 = reinterpret_cast<const float4*>(X + (size_t)m * K_DIM) + t * 4;
    float a = __ldg(asf);
    float4 v[4];
#pragma unroll
    for (int j = 0; j < 4; j++) v[j] = __ldg(x4 + j);
    float vv[16] = {v[0].x, v[0].y, v[0].z, v[0].w, v[1].x, v[1].y, v[1].z, v[1].w,
                    v[2].x, v[2].y, v[2].z, v[2].w, v[3].x, v[3].y, v[3].z, v[3].w};

    unsigned uh[16];
    float lo[16];
    float mx = 0.f;
#pragma unroll
    for (int i = 0; i < 16; i++) {
        float xi = __fdiv_rn(vv[i], a);
        __half hh = __float2half_rn(xi);
        uh[i] = (unsigned)__half_as_ushort(hh);
        lo[i] = xi - __half2float(hh);   // exact
        mx = fmaxf(mx, fabsf(lo[i]));
    }
#pragma unroll
    for (int off = 16; off > 0; off >>= 1)
        mx = fmaxf(mx, __shfl_xor_sync(0xFFFFFFFFu, mx, off));
    if (lane == 0) red[wrp] = mx;
    __syncthreads();
    if (t == 0) {
        float r = red[0];
#pragma unroll
        for (int j = 1; j < 8; j++) r = fmaxf(r, red[j]);
        float s2 = __fdiv_rn(fmaxf(r, 1e-20f), 127.0f);
        g_s2[m] = s2;
        s2_sh = s2;
    }
    __syncthreads();
    float s2 = s2_sh;

    int li[16];
#pragma unroll
    for (int i = 0; i < 16; i++)
        li[i] = (int)rintf(__fdiv_rn(lo[i], s2));   // in [-127,127]

    int tm = m >> 7;
    int m_in = m & 127;
    int mblock = m_in >> 4;
    int rr = m_in & 15;
    int ks = t >> 2, kk = t & 3, kstep = (t >> 1) & 1, khalf = t & 1;
    int rr4 = (rr & 7) * 4;
    int rhi = rr >> 3;

    // A-hi fragments: [mblock8][kk4][lane][16B]
    unsigned char* xhi = g_xhi + ((size_t)(tm * KSTAGES + ks) << 14);
#pragma unroll
    for (int p = 0; p < 8; p++) {
        int lan = rr4 + (p & 3);
        int reg = rhi + 2 * (p >> 2);
        *reinterpret_cast<uint32_t*>(xhi + mblock * 2048 + kk * 512 + lan * 16 + reg * 4) =
            uh[2 * p] | (uh[2 * p + 1] << 16);
    }
    // A-lo fragments: [mblock8][kstep2][lane][16B]
    unsigned char* xlo = g_xlo + ((size_t)(tm * KSTAGES + ks) << 13);
#pragma unroll
    for (int q = 0; q < 4; q++) {
        int lan = rr4 + q;
        int reg = rhi + 2 * khalf;
        *reinterpret_cast<uint32_t*>(xlo + mblock * 1024 + kstep * 512 + lan * 16 + reg * 4) =
            pack_s8x4(li[4 * q], li[4 * q + 1], li[4 * q + 2], li[4 * q + 3]);
    }
}

// =====================================================================
// K3: hybrid GEMM: fp16-hi HMMA + s8-lo IMMA. CTA 128x128, 8 warps,
//     warp tile 32x64. 4-stage cp.async.bulk ring, lockstep.
// =====================================================================
__global__ void __launch_bounds__(NTHREADS, 1) k_gemm() {
    extern __shared__ unsigned char smem_raw[];
    __shared__ __align__(8) uint64_t full_bar[NSTAGE];
    uint32_t base = (smem_u32(smem_raw) + 1023u) & ~1023u;
    uint32_t fb0 = smem_u32(full_bar);

    int tid = threadIdx.x;
    int lane = tid & 31;
    int w = tid >> 5;
    int wm = w & 3;        // 4 warps along M (32 rows)
    int wn = w >> 2;       // 2 warps along N (64 cols)
    int bid = blockIdx.x;
    int tn = bid & 31;
    int tm = bid >> 5;

    if (tid == 0) {
#pragma unroll
        for (int s = 0; s < NSTAGE; s++) MBAR_INIT(fb0 + s * 8, 1);
    }
    __syncthreads();

    const unsigned char* sAh = g_xhi + ((size_t)(tm * KSTAGES) << 14);
    const unsigned char* sAl = g_xlo + ((size_t)(tm * KSTAGES) << 13);
    const unsigned char* sBh = g_whi + ((size_t)(tn * KSTAGES) << 14);
    const unsigned char* sBl = g_wlo + ((size_t)(tn * KSTAGES) << 13);

    if (tid == 0) {
#pragma unroll
        for (int s = 0; s < NSTAGE; s++) {
            uint32_t st = base + s * STG_BYTES;
            uint32_t fb = fb0 + s * 8;
            MBAR_EXPECT_TX(fb, STG_BYTES);
            BULK_G2S(st + AH_OFF, sAh + ((size_t)s << 14), 16384, fb);
            BULK_G2S(st + BH_OFF, sBh + ((size_t)s << 14), 16384, fb);
            BULK_G2S(st + AL_OFF, sAl + ((size_t)s << 13), 8192, fb);
            BULK_G2S(st + BL_OFF, sBl + ((size_t)s << 13), 8192, fb);
        }
    }

    float acch[2][8][4];
    int   accl[2][8][4];
#pragma unroll
    for (int i = 0; i < 2; i++)
#pragma unroll
        for (int j = 0; j < 8; j++)
#pragma unroll
            for (int r = 0; r < 4; r++) { acch[i][j][r] = 0.f; accl[i][j][r] = 0; }

    uint32_t l16 = (uint32_t)(lane * 16);
    uint32_t l8  = (uint32_t)(lane * 8);

    for (int ksi = 0; ksi < KSTAGES; ksi++) {
        int s = ksi & (NSTAGE - 1);
        int par = (ksi / NSTAGE) & 1;
        MBAR_WAIT(fb0 + s * 8, par);
        uint32_t st = base + s * STG_BYTES;
        uint32_t ahb = st + AH_OFF + wm * 4096 + l16;
        uint32_t bhb = st + BH_OFF + wn * 2048 + l8;
        uint32_t alb = st + AL_OFF + wm * 2048 + l16;
        uint32_t blb = st + BL_OFF + wn * 2048 + l8;

        // ---- hi: fp16 HMMA ----
#pragma unroll
        for (int kk = 0; kk < 4; kk++) {
            uint32_t a0[4], a1[4];
            LDS128(a0, ahb + kk * 512);
            LDS128(a1, ahb + 2048 + kk * 512);
#pragma unroll
            for (int nb = 0; nb < 8; nb++) {
                uint32_t b0, b1;
                LDS64(b0, b1, bhb + kk * 4096 + nb * 256);
                mma16816(acch[0][nb], a0, b0, b1);
                mma16816(acch[1][nb], a1, b0, b1);
            }
        }
        // ---- lo: s8 IMMA ----
#pragma unroll
        for (int kstep = 0; kstep < 2; kstep++) {
            uint32_t a0[4], a1[4];
            LDS128(a0, alb + kstep * 512);
            LDS128(a1, alb + 1024 + kstep * 512);
#pragma unroll
            for (int nb = 0; nb < 8; nb++) {
                uint32_t b0, b1;
                LDS64(b0, b1, blb + kstep * 4096 + nb * 256);
                imma16832(accl[0][nb], a0, b0, b1);
                imma16832(accl[1][nb], a1, b0, b1);
            }
        }
        __syncthreads();
        if (ksi + NSTAGE < KSTAGES && tid == 0) {
            int ns = ksi + NSTAGE;
            uint32_t st2 = base + s * STG_BYTES;
            uint32_t fb = fb0 + s * 8;
            MBAR_EXPECT_TX(fb, STG_BYTES);
            BULK_G2S(st2 + AH_OFF, sAh + ((size_t)ns << 14), 16384, fb);
            BULK_G2S(st2 + BH_OFF, sBh + ((size_t)ns << 14), 16384, fb);
            BULK_G2S(st2 + AL_OFF, sAl + ((size_t)ns << 13), 8192, fb);
            BULK_G2S(st2 + BL_OFF, sBl + ((size_t)ns << 13), 8192, fb);
        }
    }

    // -------- epilogue: out = (hi + s2*lo + b_int)*bias_sf, ReLU, max --------
    float lmax = 0.f;
    int orow = lane >> 2;
    int ocol = (lane & 3) * 2;
    int obase = tn * TN + wn * 64;
#pragma unroll
    for (int mf = 0; mf < 2; mf++) {
        size_t m0 = (size_t)tm * TM + wm * 32 + mf * 16 + orow;
        float s2a = __ldg(&g_s2[m0]);
        float s2b = __ldg(&g_s2[m0 + 8]);
#pragma unroll
        for (int nb = 0; nb < 8; nb++) {
            int o = obase + nb * 8 + ocol;
            float bs0 = __ldg(&g_bias_sf[o]);
            float bs1 = __ldg(&g_bias_sf[o + 1]);
            float bi0 = __ldg(&g_b_int[o]);
            float bi1 = __ldg(&g_b_int[o + 1]);
            float v0 = fmaxf((acch[mf][nb][0] + s2a * (float)accl[mf][nb][0] + bi0) * bs0, 0.f);
            float v1 = fmaxf((acch[mf][nb][1] + s2a * (float)accl[mf][nb][1] + bi1) * bs1, 0.f);
            float v2 = fmaxf((acch[mf][nb][2] + s2b * (float)accl[mf][nb][2] + bi0) * bs0, 0.f);
            float v3 = fmaxf((acch[mf][nb][3] + s2b * (float)accl[mf][nb][3] + bi1) * bs1, 0.f);
            lmax = fmaxf(lmax, fmaxf(fmaxf(v0, v1), fmaxf(v2, v3)));
            *reinterpret_cast<float2*>(&g_out[m0 * N_DIM + o]) = make_float2(v0, v1);
            *reinterpret_cast<float2*>(&g_out[(m0 + 8) * N_DIM + o]) = make_float2(v2, v3);
        }
    }
#pragma unroll
    for (int off = 16; off > 0; off >>= 1)
        lmax = fmaxf(lmax, __shfl_xor_sync(0xFFFFFFFFu, lmax, off));
    if (lane == 0) atomicMax(&g_max_bits, __float_as_uint(lmax));
}

// =====================================================================
// K4: act_sf_new scalar
// =====================================================================
__global__ void k_sf(float* __restrict__ out_tail) {
    float xm = __uint_as_float(g_max_bits);
    float sf = __fdiv_rn(fmaxf(xm, 1e-8f), 255.0f);
    g_act_sf = sf;
    out_tail[0] = sf;
}

// =====================================================================
// K5: elementwise requantize (zp = 0 since min is 0 post-ReLU)
// =====================================================================
__global__ void __launch_bounds__(256) k_requant(float* __restrict__ out) {
    size_t i = ((size_t)blockIdx.x * 256 + threadIdx.x) * 4;
    float sf = g_act_sf;
    float4 v = *reinterpret_cast<const float4*>(&g_out[i]);
    float4 r;
    r.x = fminf(fmaxf(rintf(__fdiv_rn(v.x, sf)), 0.f), 255.f) * sf;
    r.y = fminf(fmaxf(rintf(__fdiv_rn(v.y, sf)), 0.f), 255.f) * sf;
    r.z = fminf(fmaxf(rintf(__fdiv_rn(v.z, sf)), 0.f), 255.f) * sf;
    r.w = fminf(fmaxf(rintf(__fdiv_rn(v.w, sf)), 0.f), 255.f) * sf;
    *reinterpret_cast<float4*>(&out[i]) = r;
}

// =====================================================================
// launch
// =====================================================================
extern "C" void kernel_launch(void* const* d_in, const int* in_sizes, int n_in,
                              void* d_out, int out_size) {
    const float* x = nullptr;
    const float* asf = nullptr;
    const float* W = nullptr;
    const float* b = nullptr;
    for (int i = 0; i < n_in; i++) {
        long s = in_sizes[i];
        if (s == (long)B_ROWS * K_DIM)      x   = (const float*)d_in[i];
        else if (s == (long)N_DIM * K_DIM)  W   = (const float*)d_in[i];
        else if (s == N_DIM)                b   = (const float*)d_in[i];
        else if (s == 1)                    asf = (const float*)d_in[i];
    }
    if (!x)   x   = (const float*)d_in[0];
    if (!asf) asf = (const float*)d_in[1];
    if (!W)   W   = (const float*)d_in[2];
    if (!b)   b   = (const float*)d_in[3];

    float* out = (float*)d_out;
    float* out_fc   = out + (size_t)B_ROWS * N_DIM;
    float* out_tail = out_fc + N_DIM;

    cudaFuncSetAttribute(k_gemm, cudaFuncAttributeMaxDynamicSharedMemorySize, SMEM_DYN);

    k_wprep<<<N_DIM, 256>>>(W, b, asf, out_fc);
    k_packx<<<B_ROWS, 256>>>(x, asf);
    k_gemm<<<(B_ROWS / TM) * (N_DIM / TN), NTHREADS, SMEM_DYN>>>();
    k_sf<<<1, 1>>>(out_tail);
    k_requant<<<(B_ROWS * N_DIM) / (256 * 4), 256>>>(out);
}

// round 7
// speedup vs baseline: 2.1254x; 2.1254x over previous
#include <cuda_runtime.h>
#include <cuda_fp16.h>
#include <cstdint>
#include <cstddef>

// ---------------- problem dims ----------------
#define B_ROWS 8192
#define K_DIM  4096
#define N_DIM  4096

// ---------------- GEMM tiling -----------------
#define TM 128
#define TN 256
#define KC 64                        // fp16 per k-stage (=128B row, one SW128 atom)
#define NSTAGE 3
#define KSTAGES (K_DIM / KC)         // 64
#define A_TILE_BYTES (TM * KC * 2)   // 16384
#define B_TILE_BYTES (TN * KC * 2)   // 32768
#define STG_BYTES (2 * A_TILE_BYTES + B_TILE_BYTES)   // 65536
#define SMEM_DYN (1024 + NSTAGE * STG_BYTES)          // 197632
#define NTHREADS 256                 // 8 compute warps, 4(m) x 2(n), warp tile 32x128

// ---------------- device scratch ----------------
__device__ __align__(1024) unsigned char g_w_packed[(size_t)N_DIM * K_DIM * 2]; // 32MB
__device__ __align__(1024) unsigned char g_x_hi[(size_t)B_ROWS * K_DIM * 2];    // 64MB
__device__ __align__(1024) unsigned char g_x_lo[(size_t)B_ROWS * K_DIM * 2];    // 64MB
__device__ float g_out[(size_t)B_ROWS * N_DIM];                                  // 128MB row-major
__device__ float g_fc_sf[N_DIM];
__device__ float g_bias_sf[N_DIM];
__device__ float g_b_int[N_DIM];
__device__ unsigned int g_max_bits;
__device__ float g_act_sf;

// ---------------- PTX helpers (baseline ISA only, no 'a' features) ----------------
__device__ __forceinline__ uint32_t smem_u32(const void* p) {
    return (uint32_t)__cvta_generic_to_shared(p);
}

#define MBAR_INIT(addr, cnt) \
    asm volatile("mbarrier.init.shared.b64 [%0], %1;" :: "r"(addr), "r"(cnt) : "memory")
#define MBAR_EXPECT_TX(addr, tx) \
    asm volatile("mbarrier.arrive.expect_tx.shared.b64 _, [%0], %1;" :: "r"(addr), "r"(tx) : "memory")

#define MBAR_WAIT(mbar_smem_addr, phase_parity) do { \
    uint32_t _mbar = (uint32_t)(mbar_smem_addr); \
    uint32_t _parity = (uint32_t)(phase_parity); \
    uint32_t _done; \
    asm volatile( \
        "{\n\t.reg .pred p;\n\t" \
        "mbarrier.try_wait.parity.acquire.cta.shared::cta.b64 p, [%1], %2;\n\t" \
        "selp.b32 %0, 1, 0, p;\n\t}" \
        : "=r"(_done) : "r"(_mbar), "r"(_parity) : "memory"); \
    if (!_done) { \
        asm volatile( \
            "{\n\t.reg .pred P1;\n\t" \
            "WAIT_LOOP_%=:\n\t" \
            "mbarrier.try_wait.parity.acquire.cta.shared::cta.b64 P1, [%0], %1, 0x989680;\n\t" \
            "@P1 bra.uni WAIT_DONE_%=;\n\t" \
            "bra.uni WAIT_LOOP_%=;\n\t" \
            "WAIT_DONE_%=:\n\t}" \
            :: "r"(_mbar), "r"(_parity) : "memory"); \
    } \
} while (0)

#define BULK_G2S(dst, src, nbytes, mbar) \
    asm volatile("cp.async.bulk.shared::cluster.global.mbarrier::complete_tx::bytes [%0], [%1], %2, [%3];" \
        :: "r"(dst), "l"(src), "r"(nbytes), "r"(mbar) : "memory")

__device__ __forceinline__ void ldsm_x4(uint32_t (&r)[4], uint32_t addr) {
    asm volatile("ldmatrix.sync.aligned.m8n8.x4.shared.b16 {%0,%1,%2,%3}, [%4];"
                 : "=r"(r[0]), "=r"(r[1]), "=r"(r[2]), "=r"(r[3]) : "r"(addr));
}

// fp32-accumulate HMMA (hi limb)
__device__ __forceinline__ void mma16816(float* c, const uint32_t* a, uint32_t b0, uint32_t b1) {
    asm volatile("mma.sync.aligned.m16n8k16.row.col.f32.f16.f16.f32 "
                 "{%0,%1,%2,%3}, {%4,%5,%6,%7}, {%8,%9}, {%0,%1,%2,%3};"
                 : "+f"(c[0]), "+f"(c[1]), "+f"(c[2]), "+f"(c[3])
                 : "r"(a[0]), "r"(a[1]), "r"(a[2]), "r"(a[3]), "r"(b0), "r"(b1));
}
// fp16-accumulate HMMA (lo limb) — 2 f16x2 accumulator regs
__device__ __forceinline__ void mma16816_h(uint32_t* c, const uint32_t* a, uint32_t b0, uint32_t b1) {
    asm volatile("mma.sync.aligned.m16n8k16.row.col.f16.f16.f16.f16 "
                 "{%0,%1}, {%2,%3,%4,%5}, {%6,%7}, {%0,%1};"
                 : "+r"(c[0]), "+r"(c[1])
                 : "r"(a[0]), "r"(a[1]), "r"(a[2]), "r"(a[3]), "r"(b0), "r"(b1));
}

// =====================================================================
// K1: merged W prep: per-row absmax -> fc_sf/bias_sf/b_int, then
//     quantize W from registers -> fp16 w_int, pre-swizzled tiles.
// =====================================================================
__global__ void __launch_bounds__(256) k_wprep(const float* __restrict__ W,
                                               const float* __restrict__ b,
                                               const float* __restrict__ asf,
                                               float* __restrict__ out_fc) {
    __shared__ float red[8];
    __shared__ float fc_sh;
    int o = blockIdx.x;
    int t = threadIdx.x;
    int lane = t & 31, wrp = t >> 5;

    const float4* w4 = reinterpret_cast<const float4*>(W + (size_t)o * K_DIM) + t * 4;
    float4 v[4];
#pragma unroll
    for (int j = 0; j < 4; j++) v[j] = __ldg(w4 + j);

    float am = 0.f;
#pragma unroll
    for (int j = 0; j < 4; j++)
        am = fmaxf(am, fmaxf(fmaxf(fabsf(v[j].x), fabsf(v[j].y)),
                             fmaxf(fabsf(v[j].z), fabsf(v[j].w))));
#pragma unroll
    for (int off = 16; off > 0; off >>= 1)
        am = fmaxf(am, __shfl_xor_sync(0xFFFFFFFFu, am, off));
    if (lane == 0) red[wrp] = am;
    __syncthreads();
    if (t == 0) {
        float m = red[0];
#pragma unroll
        for (int j = 1; j < 8; j++) m = fmaxf(m, red[j]);
        float fc = __fdiv_rn(fmaxf(m, 1e-8f), 127.0f);
        float a  = __ldg(asf);
        float bs = __fmul_rn(fc, a);
        fc_sh = fc;
        g_fc_sf[o]   = fc;
        g_bias_sf[o] = bs;
        g_b_int[o]   = rintf(__fdiv_rn(__ldg(b + o), bs));
        out_fc[o]    = fc;
        if (o == 0) g_max_bits = 0u;
    }
    __syncthreads();
    float fc = fc_sh;

    float vv[16] = {v[0].x, v[0].y, v[0].z, v[0].w, v[1].x, v[1].y, v[1].z, v[1].w,
                    v[2].x, v[2].y, v[2].z, v[2].w, v[3].x, v[3].y, v[3].z, v[3].w};
    unsigned us[16];
#pragma unroll
    for (int i = 0; i < 16; i++) {
        float r = fminf(fmaxf(rintf(__fdiv_rn(vv[i], fc)), -128.f), 127.f);
        us[i] = (unsigned)__half_as_ushort(__float2half_rn(r));
    }
    int k0 = t * 16;
    int tn = o >> 8, o_in = o & 255, ks = k0 >> 6, k_in = k0 & 63;
    size_t tilebase = ((size_t)(tn * KSTAGES + ks)) << 15;
    unsigned off0 = (unsigned)(o_in * 128 + k_in * 2);
    unsigned off1 = off0 + 16;
    off0 ^= (off0 >> 3) & 0x70;
    off1 ^= (off1 >> 3) & 0x70;
    uint4 p0, p1;
    p0.x = us[0] | (us[1] << 16);  p0.y = us[2] | (us[3] << 16);
    p0.z = us[4] | (us[5] << 16);  p0.w = us[6] | (us[7] << 16);
    p1.x = us[8] | (us[9] << 16);  p1.y = us[10] | (us[11] << 16);
    p1.z = us[12] | (us[13] << 16); p1.w = us[14] | (us[15] << 16);
    *reinterpret_cast<uint4*>(g_w_packed + tilebase + off0) = p0;
    *reinterpret_cast<uint4*>(g_w_packed + tilebase + off1) = p1;
}

// =====================================================================
// K2: x_int = x/act_sf, split into fp16 hi/lo limbs, pre-swizzled tiles
// =====================================================================
__global__ void __launch_bounds__(256) k_packx(const float* __restrict__ X,
                                               const float* __restrict__ asf) {
    unsigned g = blockIdx.x * 256u + threadIdx.x;
    int bb = (int)(g >> 9);
    int k  = (int)((g & 511u) << 3);
    float a = __ldg(asf);
    const float4* x4 = reinterpret_cast<const float4*>(X + (size_t)bb * K_DIM + k);
    float4 v0 = __ldg(x4), v1 = __ldg(x4 + 1);
    float vv[8] = {v0.x, v0.y, v0.z, v0.w, v1.x, v1.y, v1.z, v1.w};
    unsigned uh[8], ul[8];
#pragma unroll
    for (int i = 0; i < 8; i++) {
        float xi = __fdiv_rn(vv[i], a);
        __half hh = __float2half_rn(xi);
        float lo = xi - __half2float(hh);   // exact
        uh[i] = (unsigned)__half_as_ushort(hh);
        ul[i] = (unsigned)__half_as_ushort(__float2half_rn(lo));
    }
    uint4 ph, pl;
    ph.x = uh[0] | (uh[1] << 16); ph.y = uh[2] | (uh[3] << 16);
    ph.z = uh[4] | (uh[5] << 16); ph.w = uh[6] | (uh[7] << 16);
    pl.x = ul[0] | (ul[1] << 16); pl.y = ul[2] | (ul[3] << 16);
    pl.z = ul[4] | (ul[5] << 16); pl.w = ul[6] | (ul[7] << 16);
    int tm = bb >> 7, m_in = bb & 127, ks = k >> 6, k_in = k & 63;
    unsigned off = (unsigned)(m_in * 128 + k_in * 2);
    off ^= (off >> 3) & 0x70;
    size_t tb = ((size_t)(tm * KSTAGES + ks)) << 14;
    *reinterpret_cast<uint4*>(g_x_hi + tb + off) = ph;
    *reinterpret_cast<uint4*>(g_x_lo + tb + off) = pl;
}

// =====================================================================
// K3: lockstep mma.sync GEMM, 128x256 CTA tile, 8 warps (32x128 warp tile).
//     hi limb -> HMMA fp32-acc; lo limb -> HMMA fp16-acc (2x rate if HW allows).
// =====================================================================
__global__ void __launch_bounds__(NTHREADS, 1) k_gemm() {
    extern __shared__ unsigned char smem_raw[];
    __shared__ __align__(8) uint64_t full_bar[NSTAGE];
    uint32_t base = (smem_u32(smem_raw) + 1023u) & ~1023u;
    uint32_t fb0 = smem_u32(full_bar);

    int tid = threadIdx.x;
    int lane = tid & 31;
    int w = tid >> 5;
    int wm = w & 3;        // 4 warps along M (32 rows each)
    int wn = w >> 2;       // 2 warps along N (128 cols each)
    int bid = blockIdx.x;
    int tn = bid & 15;
    int tm = bid >> 4;

    if (tid == 0) {
#pragma unroll
        for (int s = 0; s < NSTAGE; s++) MBAR_INIT(fb0 + s * 8, 1);
    }
    __syncthreads();

    const unsigned char* sAh = g_x_hi + (size_t)(tm * KSTAGES) * A_TILE_BYTES;
    const unsigned char* sAl = g_x_lo + (size_t)(tm * KSTAGES) * A_TILE_BYTES;
    const unsigned char* sB  = g_w_packed + (size_t)(tn * KSTAGES) * B_TILE_BYTES;

    // prologue: fill all stages
    if (tid == 0) {
#pragma unroll
        for (int s = 0; s < NSTAGE; s++) {
            uint32_t st = base + s * STG_BYTES;
            uint32_t fb = fb0 + s * 8;
            MBAR_EXPECT_TX(fb, STG_BYTES);
            BULK_G2S(st,                    sAh + (size_t)s * A_TILE_BYTES, A_TILE_BYTES, fb);
            BULK_G2S(st + A_TILE_BYTES,     sAl + (size_t)s * A_TILE_BYTES, A_TILE_BYTES, fb);
            BULK_G2S(st + 2 * A_TILE_BYTES, sB  + (size_t)s * B_TILE_BYTES, B_TILE_BYTES, fb);
        }
    }

    int arow = lane & 15;
    int agr16 = (lane >> 4) << 4;

    // precomputed swizzled relative offsets (inner addr = st + (rel ^ kk*32))
    uint32_t aoff[2];
#pragma unroll
    for (int mf = 0; mf < 2; mf++) {
        uint32_t r = (uint32_t)((wm * 32 + mf * 16 + arow) * 128 + agr16);
        aoff[mf] = r ^ ((r >> 3) & 0x70);
    }
    uint32_t boff[8];
#pragma unroll
    for (int np = 0; np < 8; np++) {
        uint32_t r = (uint32_t)((wn * 128 + np * 16 + arow) * 128 + agr16);
        boff[np] = (r ^ ((r >> 3) & 0x70)) + 2 * A_TILE_BYTES;
    }

    float    acch[2][16][4];   // hi limb, fp32
    uint32_t accl[2][16][2];   // lo limb, fp16x2 pairs
#pragma unroll
    for (int i = 0; i < 2; i++)
#pragma unroll
        for (int j = 0; j < 16; j++) {
#pragma unroll
            for (int r = 0; r < 4; r++) acch[i][j][r] = 0.f;
            accl[i][j][0] = 0u; accl[i][j][1] = 0u;
        }

    for (int ksi = 0; ksi < KSTAGES; ksi++) {
        int s = ksi % NSTAGE;
        int par = (ksi / NSTAGE) & 1;
        MBAR_WAIT(fb0 + s * 8, par);
        uint32_t st = base + s * STG_BYTES;
#pragma unroll
        for (int kk = 0; kk < 4; kk++) {
            uint32_t kx = (uint32_t)(kk << 5);
            uint32_t afr[2][2][4];   // [limb][mf][4]
#pragma unroll
            for (int mf = 0; mf < 2; mf++) {
                uint32_t a0 = st + (aoff[mf] ^ kx);
                ldsm_x4(afr[0][mf], a0);
                ldsm_x4(afr[1][mf], a0 + A_TILE_BYTES);
            }
#pragma unroll
            for (int np = 0; np < 8; np++) {
                uint32_t bfr[4];
                ldsm_x4(bfr, st + (boff[np] ^ kx));
#pragma unroll
                for (int mf = 0; mf < 2; mf++) {
                    mma16816(acch[mf][2 * np],     afr[0][mf], bfr[0], bfr[2]);
                    mma16816(acch[mf][2 * np + 1], afr[0][mf], bfr[1], bfr[3]);
                    mma16816_h(accl[mf][2 * np],     afr[1][mf], bfr[0], bfr[2]);
                    mma16816_h(accl[mf][2 * np + 1], afr[1][mf], bfr[1], bfr[3]);
                }
            }
        }
        __syncthreads();
        if (ksi + NSTAGE < KSTAGES && tid == 0) {
            int ns = ksi + NSTAGE;
            uint32_t st2 = base + s * STG_BYTES;
            uint32_t fb = fb0 + s * 8;
            MBAR_EXPECT_TX(fb, STG_BYTES);
            BULK_G2S(st2,                    sAh + (size_t)ns * A_TILE_BYTES, A_TILE_BYTES, fb);
            BULK_G2S(st2 + A_TILE_BYTES,     sAl + (size_t)ns * A_TILE_BYTES, A_TILE_BYTES, fb);
            BULK_G2S(st2 + 2 * A_TILE_BYTES, sB  + (size_t)ns * B_TILE_BYTES, B_TILE_BYTES, fb);
        }
    }

    // -------- epilogue: out = (hi + lo + b_int)*bias_sf, ReLU, max --------
    float lmax = 0.f;
    int orow = lane >> 2;
    int ocol = (lane & 3) * 2;
    int obase = tn * TN + wn * 128;
    size_t mbase = (size_t)tm * TM + wm * 32 + orow;
#pragma unroll
    for (int mf = 0; mf < 2; mf++) {
        size_t m0 = mbase + mf * 16;
#pragma unroll
        for (int nf = 0; nf < 16; nf++) {
            int o = obase + nf * 8 + ocol;
            float bs0 = __ldg(&g_bias_sf[o]);
            float bs1 = __ldg(&g_bias_sf[o + 1]);
            float bi0 = __ldg(&g_b_int[o]);
            float bi1 = __ldg(&g_b_int[o + 1]);
            float2 lo0 = __half22float2(*reinterpret_cast<const __half2*>(&accl[mf][nf][0]));
            float2 lo1 = __half22float2(*reinterpret_cast<const __half2*>(&accl[mf][nf][1]));
            float v0 = fmaxf((acch[mf][nf][0] + lo0.x + bi0) * bs0, 0.f);
            float v1 = fmaxf((acch[mf][nf][1] + lo0.y + bi1) * bs1, 0.f);
            float v2 = fmaxf((acch[mf][nf][2] + lo1.x + bi0) * bs0, 0.f);
            float v3 = fmaxf((acch[mf][nf][3] + lo1.y + bi1) * bs1, 0.f);
            lmax = fmaxf(lmax, fmaxf(fmaxf(v0, v1), fmaxf(v2, v3)));
            *reinterpret_cast<float2*>(&g_out[m0 * N_DIM + o]) = make_float2(v0, v1);
            *reinterpret_cast<float2*>(&g_out[(m0 + 8) * N_DIM + o]) = make_float2(v2, v3);
        }
    }
#pragma unroll
    for (int off = 16; off > 0; off >>= 1)
        lmax = fmaxf(lmax, __shfl_xor_sync(0xFFFFFFFFu, lmax, off));
    if (lane == 0) atomicMax(&g_max_bits, __float_as_uint(lmax));
}

// =====================================================================
// K4: act_sf_new scalar
// =====================================================================
__global__ void k_sf(float* __restrict__ out_tail) {
    float xm = __uint_as_float(g_max_bits);
    float sf = __fdiv_rn(fmaxf(xm, 1e-8f), 255.0f);
    g_act_sf = sf;
    out_tail[0] = sf;
}

// =====================================================================
// K5: elementwise requantize (zp = 0 since min is 0 post-ReLU)
// =====================================================================
__global__ void __launch_bounds__(256) k_requant(float* __restrict__ out) {
    size_t i = ((size_t)blockIdx.x * 256 + threadIdx.x) * 4;
    float sf = g_act_sf;
    float4 v = *reinterpret_cast<const float4*>(&g_out[i]);
    float4 r;
    r.x = fminf(fmaxf(rintf(__fdiv_rn(v.x, sf)), 0.f), 255.f) * sf;
    r.y = fminf(fmaxf(rintf(__fdiv_rn(v.y, sf)), 0.f), 255.f) * sf;
    r.z = fminf(fmaxf(rintf(__fdiv_rn(v.z, sf)), 0.f), 255.f) * sf;
    r.w = fminf(fmaxf(rintf(__fdiv_rn(v.w, sf)), 0.f), 255.f) * sf;
    *reinterpret_cast<float4*>(&out[i]) = r;
}

// =====================================================================
// launch
// =====================================================================
extern "C" void kernel_launch(void* const* d_in, const int* in_sizes, int n_in,
                              void* d_out, int out_size) {
    const float* x = nullptr;
    const float* asf = nullptr;
    const float* W = nullptr;
    const float* b = nullptr;
    for (int i = 0; i < n_in; i++) {
        long s = in_sizes[i];
        if (s == (long)B_ROWS * K_DIM)      x   = (const float*)d_in[i];
        else if (s == (long)N_DIM * K_DIM)  W   = (const float*)d_in[i];
        else if (s == N_DIM)                b   = (const float*)d_in[i];
        else if (s == 1)                    asf = (const float*)d_in[i];
    }
    if (!x)   x   = (const float*)d_in[0];
    if (!asf) asf = (const float*)d_in[1];
    if (!W)   W   = (const float*)d_in[2];
    if (!b)   b   = (const float*)d_in[3];

    float* out = (float*)d_out;
    float* out_fc   = out + (size_t)B_ROWS * N_DIM;
    float* out_tail = out_fc + N_DIM;

    cudaFuncSetAttribute(k_gemm, cudaFuncAttributeMaxDynamicSharedMemorySize, SMEM_DYN);

    k_wprep<<<N_DIM, 256>>>(W, b, asf, out_fc);
    k_packx<<<(B_ROWS * (K_DIM / 8)) / 256, 256>>>(x, asf);
    k_gemm<<<(B_ROWS / TM) * (N_DIM / TN), NTHREADS, SMEM_DYN>>>();
    k_sf<<<1, 1>>>(out_tail);
    k_requant<<<(B_ROWS * N_DIM) / (256 * 4), 256>>>(out);
}